// round 10
// baseline (speedup 1.0000x reference)
#include <cuda_runtime.h>
#include <cuda_bf16.h>
#include <math.h>
#include <stdint.h>

#define BB 4
#define NSEQ 2048
#define DMODEL 1024
#define NHEADS 8
#define DH 128

// ----------------------------- scratch (device globals) --------------------
__device__ float g_E[134217728];                                  // per z: E^T [i][j] fp32
__device__ float g_P[BB * NSEQ * 3072];                           // proj out [8192][3072]
__device__ float g_APt[NSEQ * NSEQ];                              // APt[i][j] = AP[j][i]
__device__ float g_mx[32 * NSEQ];                                 // softmax max per (z, j)
__device__ float g_rinv[32 * NSEQ];                               // 1/sum(exp) per (z, j)
__device__ float g_pm[32 * 16 * NSEQ];                            // partial max
__device__ float g_ps[32 * 16 * NSEQ];                            // partial sum
__device__ __align__(128) __nv_bfloat16 g_xaug[8192 * 3072];      // A-side
__device__ __align__(128) __nv_bfloat16 g_Waug[3072 * 3072];      // B-side (Wq|Wk|Wv)
__device__ __align__(128) __nv_bfloat16 g_Woutaug[1024 * 3072];   // B-side
__device__ __align__(128) __nv_bfloat16 g_Qaug[32 * 2048 * 384];  // B-side
__device__ __align__(128) __nv_bfloat16 g_Kaug[32 * 2048 * 384];  // A-side
__device__ __align__(128) __nv_bfloat16 g_Vhi[32 * 128 * 2048];   // V^T hi
__device__ __align__(128) __nv_bfloat16 g_Vlo[32 * 128 * 2048];   // V^T lo
__device__ __align__(128) __nv_bfloat16 g_Yaug[8192 * 3072];      // A-side (built by atv)

// ----------------------------- PTX helpers ---------------------------------
__device__ __forceinline__ uint32_t smem_u32(const void* p) {
    uint32_t a;
    asm("{ .reg .u64 t; cvta.to.shared.u64 t, %1; cvt.u32.u64 %0, t; }" : "=r"(a) : "l"(p));
    return a;
}
__device__ __forceinline__ void cp16(uint32_t s, const void* g) {
    asm volatile("cp.async.cg.shared.global [%0], [%1], 16;" :: "r"(s), "l"(g));
}
__device__ __forceinline__ void cp_commit() { asm volatile("cp.async.commit_group;" ::: "memory"); }
__device__ __forceinline__ void cp_wait1() { asm volatile("cp.async.wait_group 1;" ::: "memory"); }
__device__ __forceinline__ void cp_wait0() { asm volatile("cp.async.wait_group 0;" ::: "memory"); }
__device__ __forceinline__ void ldsm4(uint32_t* r, uint32_t addr) {
    asm volatile("ldmatrix.sync.aligned.m8n8.x4.shared.b16 {%0,%1,%2,%3}, [%4];"
        : "=r"(r[0]), "=r"(r[1]), "=r"(r[2]), "=r"(r[3]) : "r"(addr));
}
__device__ __forceinline__ void mma16816(float* d, const uint32_t* a, const uint32_t* b) {
    asm volatile(
        "mma.sync.aligned.m16n8k16.row.col.f32.bf16.bf16.f32 "
        "{%0,%1,%2,%3}, {%4,%5,%6,%7}, {%8,%9}, {%0,%1,%2,%3};"
        : "+f"(d[0]), "+f"(d[1]), "+f"(d[2]), "+f"(d[3])
        : "r"(a[0]), "r"(a[1]), "r"(a[2]), "r"(a[3]), "r"(b[0]), "r"(b[1]));
}

// ----------------------------- K0: AP^T table ------------------------------
__global__ void __launch_bounds__(256) apt_kernel() {
    int idx = blockIdx.x * 256 + threadIdx.x;
    if (idx >= NSEQ * NSEQ) return;
    int i = idx / NSEQ, j = idx % NSEQ;          // APt[i][j] = AP[p=j][k=i]
    float ex = (float)(i & ~1) / (float)DMODEL;
    float denom = powf(10000.0f, ex);
    float ang = (float)j / denom;
    g_APt[idx] = (i & 1) ? cosf(ang) : sinf(ang);
}

// ----------------------------- split (fp32 -> augmented bf16) ---------------
// modeA=1: (hi, lo, hi)   modeA=0: (hi, hi, lo)
__global__ void __launch_bounds__(256) split_kernel(const float* __restrict__ S,
                                                    __nv_bfloat16* __restrict__ D,
                                                    int K, int modeA, int total) {
    int idx = blockIdx.x * 256 + threadIdx.x;
    if (idx >= total) return;
    int r = idx / K, k = idx - r * K;
    float v = S[idx];
    __nv_bfloat16 hi = __float2bfloat16(v);
    __nv_bfloat16 lo = __float2bfloat16(v - __bfloat162float(hi));
    long base = (long)r * 3 * K;
    if (modeA) {
        D[base + k] = hi; D[base + K + k] = lo; D[base + 2 * K + k] = hi;
    } else {
        D[base + k] = hi; D[base + K + k] = hi; D[base + 2 * K + k] = lo;
    }
}

// ----------------------------- Q/K aug from g_P -----------------------------
// K is the A-side (hi,lo,hi); Q the B-side (hi,hi,lo).
__global__ void __launch_bounds__(256) qksplit_kernel() {
    int idx = blockIdx.x * 256 + threadIdx.x;   // 2^23 total
    int e = idx & 127;
    int n = (idx >> 7) & 2047;
    int h = (idx >> 18) & 7;
    int b = idx >> 21;
    const float* P = g_P + ((long)(b * NSEQ + n)) * 3072 + h * DH + e;
    float q = P[0], k = P[1024];
    long base = ((long)(b * NHEADS + h) * NSEQ + n) * 384 + e;
    __nv_bfloat16 qh = __float2bfloat16(q);
    __nv_bfloat16 ql = __float2bfloat16(q - __bfloat162float(qh));
    g_Qaug[base] = qh; g_Qaug[base + 128] = qh; g_Qaug[base + 256] = ql;   // B-side
    __nv_bfloat16 kh = __float2bfloat16(k);
    __nv_bfloat16 kl = __float2bfloat16(k - __bfloat162float(kh));
    g_Kaug[base] = kh; g_Kaug[base + 128] = kl; g_Kaug[base + 256] = kh;   // A-side
}

// ----------------------------- V^T hi/lo (tiled transpose) ------------------
__global__ void __launch_bounds__(256) vtrans_kernel() {
    int z = blockIdx.z;
    int b = z >> 3, h = z & 7;
    int j0 = blockIdx.x * 32, e0 = blockIdx.y * 32;
    __shared__ float tile[32][33];
    int tx = threadIdx.x & 31, ty = threadIdx.x >> 5;
    #pragma unroll
    for (int p = 0; p < 4; p++) {
        int j = j0 + ty + p * 8;
        tile[ty + p * 8][tx] = g_P[((long)(b * NSEQ + j)) * 3072 + 2048 + h * DH + e0 + tx];
    }
    __syncthreads();
    #pragma unroll
    for (int p = 0; p < 4; p++) {
        int e = e0 + ty + p * 8;
        float v = tile[tx][ty + p * 8];
        __nv_bfloat16 hi = __float2bfloat16(v);
        __nv_bfloat16 lo = __float2bfloat16(v - __bfloat162float(hi));
        long base = (long)z * 128 * 2048 + (long)e * 2048 + j0 + tx;
        g_Vhi[base] = hi; g_Vlo[base] = lo;
    }
}

// ----------------------------- stats: partial online softmax ----------------
// Column softmax over E^T: per (z, 128-row slab), online (max, sum) per column.
__global__ void __launch_bounds__(256) stats_part_kernel() {
    int z = blockIdx.y;
    int i0 = blockIdx.x * 128;
    const float* Et = g_E + (long)z * NSEQ * NSEQ + (long)i0 * NSEQ;
    int t = threadIdx.x;
    float m[8], s[8];
    #pragma unroll
    for (int k = 0; k < 8; k++) { m[k] = -INFINITY; s[k] = 0.f; }
    for (int r = 0; r < 128; r++) {
        const float* row = Et + (long)r * NSEQ;
        #pragma unroll
        for (int k = 0; k < 8; k++) {
            float v = row[t + k * 256];
            if (v <= m[k]) s[k] += __expf(v - m[k]);
            else { s[k] = s[k] * __expf(m[k] - v) + 1.0f; m[k] = v; }
        }
    }
    float* pm = g_pm + ((long)z * 16 + blockIdx.x) * NSEQ;
    float* ps = g_ps + ((long)z * 16 + blockIdx.x) * NSEQ;
    #pragma unroll
    for (int k = 0; k < 8; k++) { pm[t + k * 256] = m[k]; ps[t + k * 256] = s[k]; }
}

// NOTE: keep (mx, rinv) as a PAIR. Fusing into s = mx + log(S) is catastrophically
// wrong in fp32 when mx = -1e9 (the +log term rounds away; exp(E-s) becomes 1.0
// instead of 1/2048 for fully-masked query columns).
__global__ void __launch_bounds__(256) stats_reduce_kernel() {
    int idx = blockIdx.x * 256 + threadIdx.x;    // 32*2048
    int z = idx >> 11, j = idx & 2047;
    const float* pm = g_pm + (long)z * 16 * NSEQ + j;
    const float* ps = g_ps + (long)z * 16 * NSEQ + j;
    float m = -INFINITY;
    #pragma unroll
    for (int p = 0; p < 16; p++) m = fmaxf(m, pm[p * NSEQ]);
    float S = 0.f;
    #pragma unroll
    for (int p = 0; p < 16; p++) S += ps[p * NSEQ] * __expf(pm[p * NSEQ] - m);
    g_mx[idx] = m;
    g_rinv[idx] = 1.0f / S;
}

// ---------------- last-head attention output (transpose + exp) --------------
__global__ void __launch_bounds__(256) outa_kernel(float* __restrict__ outA) {
    int b = blockIdx.z;
    int z = b * NHEADS + (NHEADS - 1);
    int i0 = blockIdx.x * 32, j0 = blockIdx.y * 32;
    __shared__ float tile[32][33];
    const float* Et = g_E + (long)z * NSEQ * NSEQ;
    const float* mp = g_mx + (long)z * NSEQ;
    const float* rp = g_rinv + (long)z * NSEQ;
    int tx = threadIdx.x & 31, ty = threadIdx.x >> 5;
    #pragma unroll
    for (int p = 0; p < 4; p++) {
        int il = ty + p * 8;
        tile[il][tx] = Et[(long)(i0 + il) * NSEQ + j0 + tx];
    }
    __syncthreads();
    #pragma unroll
    for (int p = 0; p < 4; p++) {
        int jl = ty + p * 8;
        float mj = mp[j0 + jl], rj = rp[j0 + jl];
        outA[((long)b * NSEQ + j0 + jl) * NSEQ + i0 + tx] = __expf(tile[tx][jl] - mj) * rj;
    }
}

// ----------------------------- generic HMMA GEMM (3-stage) -------------------
// C[m0+128][n0+128] (per z) = sum_k A[m][k]*B[n][k]; mode 0 plain, mode 1 = E^T epi.
#define GSMEM 98304

__global__ void __launch_bounds__(256) gemm_kernel(
    const __nv_bfloat16* __restrict__ A, long sAz, int lda,
    const __nv_bfloat16* __restrict__ B, long sBz, int ldb,
    int Ktot, int mode, float* __restrict__ C, long sCz, int ldc,
    const int* __restrict__ mask) {
    extern __shared__ char smem[];
    uint32_t sbase = smem_u32(smem);
    int tid = threadIdx.x, wid = tid >> 5, lane = tid & 31;
    int n0 = blockIdx.x * 128, m0 = blockIdx.y * 128, z = blockIdx.z;

    const __nv_bfloat16* Az = A + (long)z * sAz + (long)m0 * lda;
    const __nv_bfloat16* Bz = B + (long)z * sBz + (long)n0 * ldb;

    int warp_m = (wid & 3) * 32;
    int warp_n = (wid >> 2) * 64;

    float acc[2][8][4];
    #pragma unroll
    for (int i = 0; i < 2; i++)
        #pragma unroll
        for (int j = 0; j < 8; j++)
            #pragma unroll
            for (int k = 0; k < 4; k++) acc[i][j][k] = 0.f;

    uint32_t aoff[2], boff[4];
    #pragma unroll
    for (int mi = 0; mi < 2; mi++)
        aoff[mi] = (uint32_t)(warp_m + mi * 16 + (lane & 15)) * 128;
    uint32_t ake = ((lane >> 4) & 1) * 16;
    #pragma unroll
    for (int bi = 0; bi < 4; bi++)
        boff[bi] = (uint32_t)(warp_n + bi * 16 + (lane & 7) + ((lane >> 4) & 1) * 8) * 128;
    uint32_t bke = ((lane >> 3) & 1) * 16;

    int nchunk = Ktot >> 6;
    int ld_rr = tid >> 3;
    int ld_cc = tid & 7;
    #define LOAD_CHUNK(ic, buf) do {                                          \
        const __nv_bfloat16* As_ = Az + (long)(ic) * 64;                      \
        const __nv_bfloat16* Bs_ = Bz + (long)(ic) * 64;                      \
        uint32_t base_ = sbase + (buf) * 32768;                               \
        _Pragma("unroll")                                                     \
        for (int t_ = 0; t_ < 4; t_++) {                                      \
            int rr_ = ld_rr + t_ * 32;                                        \
            uint32_t off_ = (uint32_t)rr_ * 128 + ld_cc * 16;                 \
            uint32_t sw_ = off_ ^ ((off_ >> 3) & 0x70);                       \
            cp16(base_ + sw_, As_ + (long)rr_ * lda + ld_cc * 8);             \
            cp16(base_ + 16384 + sw_, Bs_ + (long)rr_ * ldb + ld_cc * 8);     \
        }                                                                     \
        cp_commit();                                                          \
    } while (0)

    LOAD_CHUNK(0, 0);
    LOAD_CHUNK(1, 1);
    for (int ic = 0; ic < nchunk; ic++) {
        if (ic + 1 < nchunk) cp_wait1(); else cp_wait0();
        __syncthreads();
        if (ic + 2 < nchunk) {
            int nb = (ic + 2) % 3;
            LOAD_CHUNK(ic + 2, nb);
        }
        uint32_t aB = sbase + (ic % 3) * 32768;
        uint32_t bB = aB + 16384;
        #pragma unroll
        for (int ks = 0; ks < 4; ks++) {
            uint32_t kcol = (uint32_t)ks * 32;
            uint32_t afr[2][4], bfr[4][4];
            #pragma unroll
            for (int mi = 0; mi < 2; mi++) {
                uint32_t off = aoff[mi] + kcol + ake;
                ldsm4(afr[mi], aB + (off ^ ((off >> 3) & 0x70)));
            }
            #pragma unroll
            for (int bi = 0; bi < 4; bi++) {
                uint32_t off = boff[bi] + kcol + bke;
                ldsm4(bfr[bi], bB + (off ^ ((off >> 3) & 0x70)));
            }
            #pragma unroll
            for (int mi = 0; mi < 2; mi++)
                #pragma unroll
                for (int ni = 0; ni < 8; ni++)
                    mma16816(acc[mi][ni], afr[mi], &bfr[ni >> 1][(ni & 1) * 2]);
        }
    }

    float* Cz = C + (long)z * sCz;
    if (mode == 1) {
        int b = z >> 3;
        #pragma unroll
        for (int mi = 0; mi < 2; mi++) {
            int r0 = m0 + warp_m + mi * 16 + (lane >> 2);
            int r1 = r0 + 8;
            int mj0 = __ldg(&mask[b * NSEQ + r0]);
            int mj1 = __ldg(&mask[b * NSEQ + r1]);
            #pragma unroll
            for (int ni = 0; ni < 8; ni++) {
                int col = n0 + warp_n + ni * 8 + (lane & 3) * 2;
                int2 mi2 = *(const int2*)&mask[b * NSEQ + col];
                float2 ap0 = *(const float2*)&g_APt[(long)r0 * NSEQ + col];
                float2 ap1 = *(const float2*)&g_APt[(long)r1 * NSEQ + col];
                float2 o0, o1;
                o0.x = (mj0 && mi2.x) ? acc[mi][ni][0] + ap0.x : -1e9f;
                o0.y = (mj0 && mi2.y) ? acc[mi][ni][1] + ap0.y : -1e9f;
                o1.x = (mj1 && mi2.x) ? acc[mi][ni][2] + ap1.x : -1e9f;
                o1.y = (mj1 && mi2.y) ? acc[mi][ni][3] + ap1.y : -1e9f;
                *(float2*)&Cz[(long)r0 * ldc + col] = o0;
                *(float2*)&Cz[(long)r1 * ldc + col] = o1;
            }
        }
    } else {
        #pragma unroll
        for (int mi = 0; mi < 2; mi++) {
            int r0 = m0 + warp_m + mi * 16 + (lane >> 2);
            int r1 = r0 + 8;
            #pragma unroll
            for (int ni = 0; ni < 8; ni++) {
                int col = n0 + warp_n + ni * 8 + (lane & 3) * 2;
                *(float2*)&Cz[(long)r0 * ldc + col] = make_float2(acc[mi][ni][0], acc[mi][ni][1]);
                *(float2*)&Cz[(long)r1 * ldc + col] = make_float2(acc[mi][ni][2], acc[mi][ni][3]);
            }
        }
    }
}

// ----------------------------- fused A^T V GEMM ------------------------------
// Per (m-tile i, z): Y[i][e] = sum_j exp(Et[i][j]-mx[j])*rinv[j] * V[j][e].
// smem: mx 8KB | rinv 8KB | stage 128x(64+4)f32 | Ahi | Alo | Vhi | Vlo
#define SM_OFF  0
#define SR_OFF  8192
#define STG_OFF 16384
#define AHI_OFF 51200
#define ALO_OFF 67584
#define VHI_OFF 83968
#define VLO_OFF 100352
#define ATV_SMEM 116736

__global__ void __launch_bounds__(256) atv_kernel() {
    extern __shared__ char smem[];
    uint32_t sb = smem_u32(smem);
    int tid = threadIdx.x, wid = tid >> 5, lane = tid & 31;
    int m0 = blockIdx.x * 128, z = blockIdx.y;
    int b = z >> 3, h = z & 7;

    {   // load mx + rinv for this z
        const float4* sm = (const float4*)(g_mx + (long)z * NSEQ);
        const float4* sr = (const float4*)(g_rinv + (long)z * NSEQ);
        float4* dm = (float4*)(smem + SM_OFF);
        float4* dr = (float4*)(smem + SR_OFF);
        #pragma unroll
        for (int q = 0; q < 2; q++) {
            dm[tid + q * 256] = sm[tid + q * 256];
            dr[tid + q * 256] = sr[tid + q * 256];
        }
    }

    const float* Et = g_E + (long)z * NSEQ * NSEQ + (long)m0 * NSEQ;
    const __nv_bfloat16* Vh = g_Vhi + (long)z * 128 * 2048;
    const __nv_bfloat16* Vl = g_Vlo + (long)z * 128 * 2048;

    float acc[2][8][4];
    #pragma unroll
    for (int i = 0; i < 2; i++)
        #pragma unroll
        for (int j = 0; j < 8; j++)
            #pragma unroll
            for (int k = 0; k < 4; k++) acc[i][j][k] = 0.f;

    int warp_m = (wid & 3) * 32;
    int warp_n = (wid >> 2) * 64;
    uint32_t aoff[2], boff[4];
    #pragma unroll
    for (int mi = 0; mi < 2; mi++)
        aoff[mi] = (uint32_t)(warp_m + mi * 16 + (lane & 15)) * 128;
    uint32_t ake = ((lane >> 4) & 1) * 16;
    #pragma unroll
    for (int bi = 0; bi < 4; bi++)
        boff[bi] = (uint32_t)(warp_n + bi * 16 + (lane & 7) + ((lane >> 4) & 1) * 8) * 128;
    uint32_t bke = ((lane >> 3) & 1) * 16;

    int er = tid >> 1, eh = tid & 1;

    #define LOAD_EST(jb) do {                                                  \
        const float* g_ = Et + (long)er * NSEQ + (jb) * 64 + eh * 32;          \
        uint32_t s0_ = sb + STG_OFF + er * 272 + eh * 128;                     \
        _Pragma("unroll")                                                      \
        for (int q_ = 0; q_ < 8; q_++) cp16(s0_ + q_ * 16, g_ + q_ * 4);       \
        cp_commit();                                                           \
    } while (0)

    #define LOAD_VT(jb) do {                                                   \
        _Pragma("unroll")                                                      \
        for (int q_ = 0; q_ < 4; q_++) {                                       \
            uint32_t off_ = (uint32_t)er * 128 + (eh * 4 + q_) * 16;           \
            uint32_t sw_ = off_ ^ ((off_ >> 3) & 0x70);                        \
            long gb_ = (long)er * 2048 + (jb) * 64 + (eh * 4 + q_) * 8;        \
            cp16(sb + VHI_OFF + sw_, Vh + gb_);                                \
            cp16(sb + VLO_OFF + sw_, Vl + gb_);                                \
        }                                                                      \
        cp_commit();                                                           \
    } while (0)

    LOAD_EST(0);
    LOAD_VT(0);
    for (int jb = 0; jb < 32; jb++) {
        cp_wait0();
        __syncthreads();
        // --- exp + split phase: stage -> Ahi/Alo tiles
        {
            const float* mrow = (const float*)(smem + SM_OFF) + jb * 64 + eh * 32;
            const float* rrow = (const float*)(smem + SR_OFF) + jb * 64 + eh * 32;
            const char* stg = smem + STG_OFF + er * 272 + eh * 128;
            #pragma unroll
            for (int q = 0; q < 4; q++) {
                float4 v0 = *(const float4*)(stg + q * 32);
                float4 v1 = *(const float4*)(stg + q * 32 + 16);
                float4 ma = *(const float4*)(mrow + q * 8);
                float4 mb = *(const float4*)(mrow + q * 8 + 4);
                float4 ra = *(const float4*)(rrow + q * 8);
                float4 rb = *(const float4*)(rrow + q * 8 + 4);
                float a[8];
                a[0] = __expf(v0.x - ma.x) * ra.x;  a[1] = __expf(v0.y - ma.y) * ra.y;
                a[2] = __expf(v0.z - ma.z) * ra.z;  a[3] = __expf(v0.w - ma.w) * ra.w;
                a[4] = __expf(v1.x - mb.x) * rb.x;  a[5] = __expf(v1.y - mb.y) * rb.y;
                a[6] = __expf(v1.z - mb.z) * rb.z;  a[7] = __expf(v1.w - mb.w) * rb.w;
                __nv_bfloat16 hv[8], lv[8];
                #pragma unroll
                for (int e = 0; e < 8; e++) {
                    hv[e] = __float2bfloat16(a[e]);
                    lv[e] = __float2bfloat16(a[e] - __bfloat162float(hv[e]));
                }
                uint32_t off = (uint32_t)er * 128 + eh * 64 + q * 16;
                uint32_t sw = off ^ ((off >> 3) & 0x70);
                *(uint4*)(smem + AHI_OFF + sw) = *(uint4*)hv;
                *(uint4*)(smem + ALO_OFF + sw) = *(uint4*)lv;
            }
        }
        __syncthreads();
        if (jb + 1 < 32) LOAD_EST(jb + 1);
        // --- MMA phase: 3 compensation terms
        const uint32_t aT[3] = {AHI_OFF, ALO_OFF, AHI_OFF};
        const uint32_t bT[3] = {VHI_OFF, VHI_OFF, VLO_OFF};
        #pragma unroll
        for (int t = 0; t < 3; t++) {
            uint32_t aB = sb + aT[t], bB = sb + bT[t];
            #pragma unroll
            for (int ks = 0; ks < 4; ks++) {
                uint32_t kcol = (uint32_t)ks * 32;
                uint32_t afr[2][4], bfr[4][4];
                #pragma unroll
                for (int mi = 0; mi < 2; mi++) {
                    uint32_t off = aoff[mi] + kcol + ake;
                    ldsm4(afr[mi], aB + (off ^ ((off >> 3) & 0x70)));
                }
                #pragma unroll
                for (int bi = 0; bi < 4; bi++) {
                    uint32_t off = boff[bi] + kcol + bke;
                    ldsm4(bfr[bi], bB + (off ^ ((off >> 3) & 0x70)));
                }
                #pragma unroll
                for (int mi = 0; mi < 2; mi++)
                    #pragma unroll
                    for (int ni = 0; ni < 8; ni++)
                        mma16816(acc[mi][ni], afr[mi], &bfr[ni >> 1][(ni & 1) * 2]);
            }
        }
        __syncthreads();
        if (jb + 1 < 32) LOAD_VT(jb + 1);
    }

    // --- epilogue: write Yaug (hi, lo, hi) directly
    #pragma unroll
    for (int mi = 0; mi < 2; mi++) {
        #pragma unroll
        for (int half = 0; half < 2; half++) {
            int rr = warp_m + mi * 16 + (lane >> 2) + half * 8;
            __nv_bfloat16* Yr = g_Yaug + ((long)(b * NSEQ + m0 + rr)) * 3072 + h * DH;
            #pragma unroll
            for (int ni = 0; ni < 8; ni++) {
                int col = warp_n + ni * 8 + (lane & 3) * 2;
                float y0 = acc[mi][ni][half * 2 + 0];
                float y1 = acc[mi][ni][half * 2 + 1];
                __nv_bfloat16 h0 = __float2bfloat16(y0);
                __nv_bfloat16 h1 = __float2bfloat16(y1);
                __nv_bfloat16 l0 = __float2bfloat16(y0 - __bfloat162float(h0));
                __nv_bfloat16 l1 = __float2bfloat16(y1 - __bfloat162float(h1));
                __nv_bfloat162 hi2; hi2.x = h0; hi2.y = h1;
                __nv_bfloat162 lo2; lo2.x = l0; lo2.y = l1;
                *(__nv_bfloat162*)&Yr[col] = hi2;
                *(__nv_bfloat162*)&Yr[1024 + col] = lo2;
                *(__nv_bfloat162*)&Yr[2048 + col] = hi2;
            }
        }
    }
}

// ----------------------------- launch ---------------------------------------
extern "C" void kernel_launch(void* const* d_in, const int* in_sizes, int n_in,
                              void* d_out, int out_size) {
    const float* x    = (const float*)d_in[0];
    const int*   mask = (const int*)d_in[1];
    const float* Wq   = (const float*)d_in[2];
    const float* Wk   = (const float*)d_in[3];
    const float* Wv   = (const float*)d_in[4];
    const float* Wout = (const float*)d_in[5];
    float* out = (float*)d_out;

    const long long out_elems = (long long)BB * NSEQ * DMODEL;
    const long long att_elems = (long long)BB * NSEQ * NSEQ;
    float* outA = ((long long)out_size >= out_elems + att_elems) ? out + out_elems : nullptr;

    cudaFuncSetAttribute(gemm_kernel, cudaFuncAttributeMaxDynamicSharedMemorySize, GSMEM);
    cudaFuncSetAttribute(atv_kernel, cudaFuncAttributeMaxDynamicSharedMemorySize, ATV_SMEM);

    __nv_bfloat16 *p_xaug, *p_Waug, *p_Woutaug, *p_Qaug, *p_Kaug, *p_Yaug;
    float *p_P, *p_E;
    cudaGetSymbolAddress((void**)&p_xaug, g_xaug);
    cudaGetSymbolAddress((void**)&p_Waug, g_Waug);
    cudaGetSymbolAddress((void**)&p_Woutaug, g_Woutaug);
    cudaGetSymbolAddress((void**)&p_Qaug, g_Qaug);
    cudaGetSymbolAddress((void**)&p_Kaug, g_Kaug);
    cudaGetSymbolAddress((void**)&p_Yaug, g_Yaug);
    cudaGetSymbolAddress((void**)&p_P, g_P);
    cudaGetSymbolAddress((void**)&p_E, g_E);

    apt_kernel<<<(NSEQ * NSEQ) / 256, 256>>>();

    split_kernel<<<(8192 * 1024) / 256, 256>>>(x, p_xaug, 1024, 1, 8192 * 1024);
    split_kernel<<<(1024 * 1024) / 256, 256>>>(Wq,   p_Waug,               1024, 0, 1024 * 1024);
    split_kernel<<<(1024 * 1024) / 256, 256>>>(Wk,   p_Waug + 1024 * 3072, 1024, 0, 1024 * 1024);
    split_kernel<<<(1024 * 1024) / 256, 256>>>(Wv,   p_Waug + 2048 * 3072, 1024, 0, 1024 * 1024);
    split_kernel<<<(1024 * 1024) / 256, 256>>>(Wout, p_Woutaug,            1024, 0, 1024 * 1024);

    // QKV projection
    gemm_kernel<<<dim3(3072 / 128, 8192 / 128, 1), 256, GSMEM>>>(
        p_xaug, 0, 3072, p_Waug, 0, 3072, 3072, 0, p_P, 0, 3072, mask);

    qksplit_kernel<<<(1 << 23) / 256, 256>>>();
    vtrans_kernel<<<dim3(NSEQ / 32, DH / 32, 32), 256>>>();

    // E^T = (K Q^T) + AP^T, masked  (rows = key i, cols = query j)
    gemm_kernel<<<dim3(NSEQ / 128, NSEQ / 128, 32), 256, GSMEM>>>(
        p_Kaug, (long)NSEQ * 384, 384, p_Qaug, (long)NSEQ * 384, 384,
        384, 1, p_E, (long)NSEQ * NSEQ, NSEQ, mask);

    stats_part_kernel<<<dim3(16, 32), 256>>>();
    stats_reduce_kernel<<<(32 * NSEQ) / 256, 256>>>();
    if (outA) outa_kernel<<<dim3(NSEQ / 32, NSEQ / 32, BB), 256>>>(outA);

    // fused Y = A^T V  -> writes Yaug directly
    atv_kernel<<<dim3(16, 32), 256, ATV_SMEM>>>();

    // out = Y Wout^T
    gemm_kernel<<<dim3(1024 / 128, 8192 / 128, 1), 256, GSMEM>>>(
        p_Yaug, 0, 3072, p_Woutaug, 0, 3072, 3072, 0, out, 0, 1024, mask);
}

// round 11
// speedup vs baseline: 1.0947x; 1.0947x over previous
#include <cuda_runtime.h>
#include <cuda_bf16.h>
#include <math.h>
#include <stdint.h>

#define BB 4
#define NSEQ 2048
#define DMODEL 1024
#define NHEADS 8
#define DH 128

// ----------------------------- scratch (device globals) --------------------
__device__ float g_E[134217728];                                  // per z: E^T [i][j] fp32
__device__ float g_P[BB * NSEQ * 3072];                           // proj out [8192][3072]
__device__ float g_APt[NSEQ * NSEQ];                              // APt[i][j] = AP[j][i]
__device__ float g_mx[32 * NSEQ];                                 // softmax max per (z, j)
__device__ float g_rinv[32 * NSEQ];                               // 1/sum(exp) per (z, j)
__device__ float g_pm[32 * 16 * NSEQ];                            // partial max
__device__ float g_ps[32 * 16 * NSEQ];                            // partial sum
__device__ __align__(128) __nv_bfloat16 g_xaug[8192 * 3072];      // A-side
__device__ __align__(128) __nv_bfloat16 g_Waug[3072 * 3072];      // B-side (Wq|Wk|Wv)
__device__ __align__(128) __nv_bfloat16 g_Woutaug[1024 * 3072];   // B-side
__device__ __align__(128) __nv_bfloat16 g_Qaug[32 * 2048 * 384];  // B-side
__device__ __align__(128) __nv_bfloat16 g_Kaug[32 * 2048 * 384];  // A-side
__device__ __align__(128) __nv_bfloat16 g_Vhi[32 * 128 * 2048];   // V^T hi
__device__ __align__(128) __nv_bfloat16 g_Vlo[32 * 128 * 2048];   // V^T lo
__device__ __align__(128) __nv_bfloat16 g_Yaug[8192 * 3072];      // A-side (built by atv)

// ----------------------------- PTX helpers ---------------------------------
__device__ __forceinline__ uint32_t smem_u32(const void* p) {
    uint32_t a;
    asm("{ .reg .u64 t; cvta.to.shared.u64 t, %1; cvt.u32.u64 %0, t; }" : "=r"(a) : "l"(p));
    return a;
}
__device__ __forceinline__ void cp16(uint32_t s, const void* g) {
    asm volatile("cp.async.cg.shared.global [%0], [%1], 16;" :: "r"(s), "l"(g));
}
__device__ __forceinline__ void cp_commit() { asm volatile("cp.async.commit_group;" ::: "memory"); }
__device__ __forceinline__ void cp_wait1() { asm volatile("cp.async.wait_group 1;" ::: "memory"); }
__device__ __forceinline__ void cp_wait0() { asm volatile("cp.async.wait_group 0;" ::: "memory"); }
__device__ __forceinline__ void ldsm4(uint32_t* r, uint32_t addr) {
    asm volatile("ldmatrix.sync.aligned.m8n8.x4.shared.b16 {%0,%1,%2,%3}, [%4];"
        : "=r"(r[0]), "=r"(r[1]), "=r"(r[2]), "=r"(r[3]) : "r"(addr));
}
__device__ __forceinline__ void mma16816(float* d, const uint32_t* a, const uint32_t* b) {
    asm volatile(
        "mma.sync.aligned.m16n8k16.row.col.f32.bf16.bf16.f32 "
        "{%0,%1,%2,%3}, {%4,%5,%6,%7}, {%8,%9}, {%0,%1,%2,%3};"
        : "+f"(d[0]), "+f"(d[1]), "+f"(d[2]), "+f"(d[3])
        : "r"(a[0]), "r"(a[1]), "r"(a[2]), "r"(a[3]), "r"(b[0]), "r"(b[1]));
}

// ----------------------------- AP^T table ----------------------------------
__global__ void __launch_bounds__(256) apt_kernel() {
    int idx = blockIdx.x * 256 + threadIdx.x;
    if (idx >= NSEQ * NSEQ) return;
    int i = idx / NSEQ, j = idx % NSEQ;          // APt[i][j] = AP[p=j][k=i]
    float ex = (float)(i & ~1) / (float)DMODEL;
    float denom = powf(10000.0f, ex);
    float ang = (float)j / denom;
    g_APt[idx] = (i & 1) ? cosf(ang) : sinf(ang);
}

// ----------------------------- split (fp32 -> augmented bf16) ---------------
// modeA=1: (hi, lo, hi)   modeA=0: (hi, hi, lo)
__global__ void __launch_bounds__(256) split_kernel(const float* __restrict__ S,
                                                    __nv_bfloat16* __restrict__ D,
                                                    int K, int modeA, int total) {
    int idx = blockIdx.x * 256 + threadIdx.x;
    if (idx >= total) return;
    int r = idx / K, k = idx - r * K;
    float v = S[idx];
    __nv_bfloat16 hi = __float2bfloat16(v);
    __nv_bfloat16 lo = __float2bfloat16(v - __bfloat162float(hi));
    long base = (long)r * 3 * K;
    if (modeA) {
        D[base + k] = hi; D[base + K + k] = lo; D[base + 2 * K + k] = hi;
    } else {
        D[base + k] = hi; D[base + K + k] = hi; D[base + 2 * K + k] = lo;
    }
}

// ----------------------------- Q/K aug from g_P -----------------------------
// K is the A-side (hi,lo,hi); Q the B-side (hi,hi,lo).
__global__ void __launch_bounds__(256) qksplit_kernel() {
    int idx = blockIdx.x * 256 + threadIdx.x;   // 2^23 total
    int e = idx & 127;
    int n = (idx >> 7) & 2047;
    int h = (idx >> 18) & 7;
    int b = idx >> 21;
    const float* P = g_P + ((long)(b * NSEQ + n)) * 3072 + h * DH + e;
    float q = P[0], k = P[1024];
    long base = ((long)(b * NHEADS + h) * NSEQ + n) * 384 + e;
    __nv_bfloat16 qh = __float2bfloat16(q);
    __nv_bfloat16 ql = __float2bfloat16(q - __bfloat162float(qh));
    g_Qaug[base] = qh; g_Qaug[base + 128] = qh; g_Qaug[base + 256] = ql;   // B-side
    __nv_bfloat16 kh = __float2bfloat16(k);
    __nv_bfloat16 kl = __float2bfloat16(k - __bfloat162float(kh));
    g_Kaug[base] = kh; g_Kaug[base + 128] = kl; g_Kaug[base + 256] = kh;   // A-side
}

// ----------------------------- V^T hi/lo (tiled transpose) ------------------
__global__ void __launch_bounds__(256) vtrans_kernel() {
    int z = blockIdx.z;
    int b = z >> 3, h = z & 7;
    int j0 = blockIdx.x * 32, e0 = blockIdx.y * 32;
    __shared__ float tile[32][33];
    int tx = threadIdx.x & 31, ty = threadIdx.x >> 5;
    #pragma unroll
    for (int p = 0; p < 4; p++) {
        int j = j0 + ty + p * 8;
        tile[ty + p * 8][tx] = g_P[((long)(b * NSEQ + j)) * 3072 + 2048 + h * DH + e0 + tx];
    }
    __syncthreads();
    #pragma unroll
    for (int p = 0; p < 4; p++) {
        int e = e0 + ty + p * 8;
        float v = tile[tx][ty + p * 8];
        __nv_bfloat16 hi = __float2bfloat16(v);
        __nv_bfloat16 lo = __float2bfloat16(v - __bfloat162float(hi));
        long base = (long)z * 128 * 2048 + (long)e * 2048 + j0 + tx;
        g_Vhi[base] = hi; g_Vlo[base] = lo;
    }
}

// NOTE: keep (mx, rinv) as a PAIR. Fusing into s = mx + log(S) is catastrophically
// wrong in fp32 when mx = -1e9 (exp(E-s) becomes 1.0 instead of 1/2048).
__global__ void __launch_bounds__(256) stats_reduce_kernel() {
    int idx = blockIdx.x * 256 + threadIdx.x;    // 32*2048
    int z = idx >> 11, j = idx & 2047;
    const float* pm = g_pm + (long)z * 16 * NSEQ + j;
    const float* ps = g_ps + (long)z * 16 * NSEQ + j;
    float m = -INFINITY;
    #pragma unroll
    for (int p = 0; p < 16; p++) m = fmaxf(m, pm[p * NSEQ]);
    float S = 0.f;
    #pragma unroll
    for (int p = 0; p < 16; p++) S += ps[p * NSEQ] * __expf(pm[p * NSEQ] - m);
    g_mx[idx] = m;
    g_rinv[idx] = 1.0f / S;
}

// ---------------- last-head attention output (transpose + exp) --------------
__global__ void __launch_bounds__(256) outa_kernel(float* __restrict__ outA) {
    int b = blockIdx.z;
    int z = b * NHEADS + (NHEADS - 1);
    int i0 = blockIdx.x * 32, j0 = blockIdx.y * 32;
    __shared__ float tile[32][33];
    const float* Et = g_E + (long)z * NSEQ * NSEQ;
    const float* mp = g_mx + (long)z * NSEQ;
    const float* rp = g_rinv + (long)z * NSEQ;
    int tx = threadIdx.x & 31, ty = threadIdx.x >> 5;
    #pragma unroll
    for (int p = 0; p < 4; p++) {
        int il = ty + p * 8;
        tile[il][tx] = Et[(long)(i0 + il) * NSEQ + j0 + tx];
    }
    __syncthreads();
    #pragma unroll
    for (int p = 0; p < 4; p++) {
        int jl = ty + p * 8;
        float mj = mp[j0 + jl], rj = rp[j0 + jl];
        outA[((long)b * NSEQ + j0 + jl) * NSEQ + i0 + tx] = __expf(tile[tx][jl] - mj) * rj;
    }
}

// ----------------------------- generic HMMA GEMM (2-stage) -------------------
// C[m0+128][n0+128] (per z) = sum_k A[m][k]*B[n][k].
// mode 0: plain store. mode 1: E^T epilogue (+AP^T, mask) + fused column stats.
#define GSMEM 65536

__global__ void __launch_bounds__(256) gemm_kernel(
    const __nv_bfloat16* __restrict__ A, long sAz, int lda,
    const __nv_bfloat16* __restrict__ B, long sBz, int ldb,
    int Ktot, int mode, float* __restrict__ C, long sCz, int ldc,
    const int* __restrict__ mask) {
    extern __shared__ char smem[];
    __shared__ float s_mx[4][128];
    __shared__ float s_sm[4][128];
    uint32_t sbase = smem_u32(smem);
    int tid = threadIdx.x, wid = tid >> 5, lane = tid & 31;
    int n0 = blockIdx.x * 128, m0 = blockIdx.y * 128, z = blockIdx.z;

    const __nv_bfloat16* Az = A + (long)z * sAz + (long)m0 * lda;
    const __nv_bfloat16* Bz = B + (long)z * sBz + (long)n0 * ldb;

    int warp_m = (wid & 3) * 32;
    int warp_n = (wid >> 2) * 64;

    float acc[2][8][4];
    #pragma unroll
    for (int i = 0; i < 2; i++)
        #pragma unroll
        for (int j = 0; j < 8; j++)
            #pragma unroll
            for (int k = 0; k < 4; k++) acc[i][j][k] = 0.f;

    uint32_t aoff[2], boff[4];
    #pragma unroll
    for (int mi = 0; mi < 2; mi++)
        aoff[mi] = (uint32_t)(warp_m + mi * 16 + (lane & 15)) * 128;
    uint32_t ake = ((lane >> 4) & 1) * 16;
    #pragma unroll
    for (int bi = 0; bi < 4; bi++)
        boff[bi] = (uint32_t)(warp_n + bi * 16 + (lane & 7) + ((lane >> 4) & 1) * 8) * 128;
    uint32_t bke = ((lane >> 3) & 1) * 16;

    int nchunk = Ktot >> 6;
    int ld_rr = tid >> 3;
    int ld_cc = tid & 7;
    #define LOAD_CHUNK(ic, buf) do {                                          \
        const __nv_bfloat16* As_ = Az + (long)(ic) * 64;                      \
        const __nv_bfloat16* Bs_ = Bz + (long)(ic) * 64;                      \
        uint32_t base_ = sbase + (buf) * 32768;                               \
        _Pragma("unroll")                                                     \
        for (int t_ = 0; t_ < 4; t_++) {                                      \
            int rr_ = ld_rr + t_ * 32;                                        \
            uint32_t off_ = (uint32_t)rr_ * 128 + ld_cc * 16;                 \
            uint32_t sw_ = off_ ^ ((off_ >> 3) & 0x70);                       \
            cp16(base_ + sw_, As_ + (long)rr_ * lda + ld_cc * 8);             \
            cp16(base_ + 16384 + sw_, Bs_ + (long)rr_ * ldb + ld_cc * 8);     \
        }                                                                     \
        cp_commit();                                                          \
    } while (0)

    LOAD_CHUNK(0, 0);
    for (int ic = 0; ic < nchunk; ic++) {
        int buf = ic & 1;
        if (ic + 1 < nchunk) { LOAD_CHUNK(ic + 1, buf ^ 1); cp_wait1(); }
        else cp_wait0();
        __syncthreads();

        uint32_t aB = sbase + buf * 32768;
        uint32_t bB = aB + 16384;
        #pragma unroll
        for (int ks = 0; ks < 4; ks++) {
            uint32_t kcol = (uint32_t)ks * 32;
            uint32_t afr[2][4], bfr[4][4];
            #pragma unroll
            for (int mi = 0; mi < 2; mi++) {
                uint32_t off = aoff[mi] + kcol + ake;
                ldsm4(afr[mi], aB + (off ^ ((off >> 3) & 0x70)));
            }
            #pragma unroll
            for (int bi = 0; bi < 4; bi++) {
                uint32_t off = boff[bi] + kcol + bke;
                ldsm4(bfr[bi], bB + (off ^ ((off >> 3) & 0x70)));
            }
            #pragma unroll
            for (int mi = 0; mi < 2; mi++)
                #pragma unroll
                for (int ni = 0; ni < 8; ni++)
                    mma16816(acc[mi][ni], afr[mi], &bfr[ni >> 1][(ni & 1) * 2]);
        }
        __syncthreads();
    }

    float* Cz = C + (long)z * sCz;
    if (mode == 1) {
        int b = z >> 3;
        float ov[2][8][4];
        #pragma unroll
        for (int mi = 0; mi < 2; mi++) {
            int r0 = m0 + warp_m + mi * 16 + (lane >> 2);
            int r1 = r0 + 8;
            int mj0 = __ldg(&mask[b * NSEQ + r0]);
            int mj1 = __ldg(&mask[b * NSEQ + r1]);
            #pragma unroll
            for (int ni = 0; ni < 8; ni++) {
                int col = n0 + warp_n + ni * 8 + (lane & 3) * 2;
                int2 mi2 = *(const int2*)&mask[b * NSEQ + col];
                float2 ap0 = *(const float2*)&g_APt[(long)r0 * NSEQ + col];
                float2 ap1 = *(const float2*)&g_APt[(long)r1 * NSEQ + col];
                ov[mi][ni][0] = (mj0 && mi2.x) ? acc[mi][ni][0] + ap0.x : -1e9f;
                ov[mi][ni][1] = (mj0 && mi2.y) ? acc[mi][ni][1] + ap0.y : -1e9f;
                ov[mi][ni][2] = (mj1 && mi2.x) ? acc[mi][ni][2] + ap1.x : -1e9f;
                ov[mi][ni][3] = (mj1 && mi2.y) ? acc[mi][ni][3] + ap1.y : -1e9f;
                *(float2*)&Cz[(long)r0 * ldc + col] = make_float2(ov[mi][ni][0], ov[mi][ni][1]);
                *(float2*)&Cz[(long)r1 * ldc + col] = make_float2(ov[mi][ni][2], ov[mi][ni][3]);
            }
        }
        // fused per-column (j) stats over this block's 128 rows (i)
        #pragma unroll
        for (int k = 0; k < 16; k++) {
            int ni = k >> 1, c = k & 1;
            float m = fmaxf(fmaxf(ov[0][ni][c], ov[0][ni][2 + c]),
                            fmaxf(ov[1][ni][c], ov[1][ni][2 + c]));
            #pragma unroll
            for (int d = 4; d < 32; d <<= 1)
                m = fmaxf(m, __shfl_xor_sync(0xffffffffu, m, d));
            if ((lane >> 2) == 0)
                s_mx[wid & 3][warp_n + ni * 8 + (lane & 3) * 2 + c] = m;
        }
        __syncthreads();
        #pragma unroll
        for (int k = 0; k < 16; k++) {
            int ni = k >> 1, c = k & 1;
            int cc = warp_n + ni * 8 + (lane & 3) * 2 + c;
            float fm = fmaxf(fmaxf(s_mx[0][cc], s_mx[1][cc]),
                             fmaxf(s_mx[2][cc], s_mx[3][cc]));
            float s = __expf(ov[0][ni][c] - fm) + __expf(ov[0][ni][2 + c] - fm)
                    + __expf(ov[1][ni][c] - fm) + __expf(ov[1][ni][2 + c] - fm);
            #pragma unroll
            for (int d = 4; d < 32; d <<= 1)
                s += __shfl_xor_sync(0xffffffffu, s, d);
            if ((lane >> 2) == 0)
                s_sm[wid & 3][cc] = s;
        }
        __syncthreads();
        if (tid < 128) {
            float m = fmaxf(fmaxf(s_mx[0][tid], s_mx[1][tid]),
                            fmaxf(s_mx[2][tid], s_mx[3][tid]));
            float S = s_sm[0][tid] + s_sm[1][tid] + s_sm[2][tid] + s_sm[3][tid];
            long o = ((long)z * 16 + blockIdx.y) * NSEQ + n0 + tid;
            g_pm[o] = m;
            g_ps[o] = S;
        }
    } else {
        #pragma unroll
        for (int mi = 0; mi < 2; mi++) {
            int r0 = m0 + warp_m + mi * 16 + (lane >> 2);
            int r1 = r0 + 8;
            #pragma unroll
            for (int ni = 0; ni < 8; ni++) {
                int col = n0 + warp_n + ni * 8 + (lane & 3) * 2;
                *(float2*)&Cz[(long)r0 * ldc + col] = make_float2(acc[mi][ni][0], acc[mi][ni][1]);
                *(float2*)&Cz[(long)r1 * ldc + col] = make_float2(acc[mi][ni][2], acc[mi][ni][3]);
            }
        }
    }
}

// ----------------------------- fused A^T V GEMM ------------------------------
// Per (m-tile i, z): Y[i][e] = sum_j exp(Et[i][j]-mx[j])*rinv[j] * V[j][e].
// smem: mx 8K | rinv 8K | stage 128x(64+4)f32 | Ahi | Alo | V double-buffered
#define SM_OFF   0
#define SR_OFF   8192
#define STG_OFF  16384
#define AHI_OFF  51200
#define ALO_OFF  67584
#define VBASE    83968
#define ATV_SMEM 149504

__global__ void __launch_bounds__(256) atv_kernel() {
    extern __shared__ char smem[];
    uint32_t sb = smem_u32(smem);
    int tid = threadIdx.x, wid = tid >> 5, lane = tid & 31;
    int m0 = blockIdx.x * 128, z = blockIdx.y;
    int b = z >> 3, h = z & 7;

    {   // load mx + rinv for this z
        const float4* sm = (const float4*)(g_mx + (long)z * NSEQ);
        const float4* sr = (const float4*)(g_rinv + (long)z * NSEQ);
        float4* dm = (float4*)(smem + SM_OFF);
        float4* dr = (float4*)(smem + SR_OFF);
        #pragma unroll
        for (int q = 0; q < 2; q++) {
            dm[tid + q * 256] = sm[tid + q * 256];
            dr[tid + q * 256] = sr[tid + q * 256];
        }
    }

    const float* Et = g_E + (long)z * NSEQ * NSEQ + (long)m0 * NSEQ;
    const __nv_bfloat16* Vh = g_Vhi + (long)z * 128 * 2048;
    const __nv_bfloat16* Vl = g_Vlo + (long)z * 128 * 2048;

    float acc[2][8][4];
    #pragma unroll
    for (int i = 0; i < 2; i++)
        #pragma unroll
        for (int j = 0; j < 8; j++)
            #pragma unroll
            for (int k = 0; k < 4; k++) acc[i][j][k] = 0.f;

    int warp_m = (wid & 3) * 32;
    int warp_n = (wid >> 2) * 64;
    uint32_t aoff[2], boff[4];
    #pragma unroll
    for (int mi = 0; mi < 2; mi++)
        aoff[mi] = (uint32_t)(warp_m + mi * 16 + (lane & 15)) * 128;
    uint32_t ake = ((lane >> 4) & 1) * 16;
    #pragma unroll
    for (int bi = 0; bi < 4; bi++)
        boff[bi] = (uint32_t)(warp_n + bi * 16 + (lane & 7) + ((lane >> 4) & 1) * 8) * 128;
    uint32_t bke = ((lane >> 3) & 1) * 16;

    int er = tid >> 1, eh = tid & 1;

    #define LOAD_EST(jb) do {                                                  \
        const float* g_ = Et + (long)er * NSEQ + (jb) * 64 + eh * 32;          \
        uint32_t s0_ = sb + STG_OFF + er * 272 + eh * 128;                     \
        _Pragma("unroll")                                                      \
        for (int q_ = 0; q_ < 8; q_++) cp16(s0_ + q_ * 16, g_ + q_ * 4);       \
    } while (0)

    #define LOAD_VT(jb, vb) do {                                               \
        uint32_t vb_ = sb + VBASE + (vb) * 32768;                              \
        _Pragma("unroll")                                                      \
        for (int q_ = 0; q_ < 4; q_++) {                                       \
            uint32_t off_ = (uint32_t)er * 128 + (eh * 4 + q_) * 16;           \
            uint32_t sw_ = off_ ^ ((off_ >> 3) & 0x70);                        \
            long gb_ = (long)er * 2048 + (jb) * 64 + (eh * 4 + q_) * 8;        \
            cp16(vb_ + sw_, Vh + gb_);                                         \
            cp16(vb_ + 16384 + sw_, Vl + gb_);                                 \
        }                                                                      \
    } while (0)

    LOAD_EST(0);
    LOAD_VT(0, 0);
    cp_commit();
    for (int jb = 0; jb < 32; jb++) {
        cp_wait0();
        __syncthreads();
        // --- exp phase: stage -> Ahi/Alo tiles
        {
            const float* mrow = (const float*)(smem + SM_OFF) + jb * 64 + eh * 32;
            const float* rrow = (const float*)(smem + SR_OFF) + jb * 64 + eh * 32;
            const char* stg = smem + STG_OFF + er * 272 + eh * 128;
            #pragma unroll
            for (int q = 0; q < 4; q++) {
                float4 v0 = *(const float4*)(stg + q * 32);
                float4 v1 = *(const float4*)(stg + q * 32 + 16);
                float4 ma = *(const float4*)(mrow + q * 8);
                float4 mb = *(const float4*)(mrow + q * 8 + 4);
                float4 ra = *(const float4*)(rrow + q * 8);
                float4 rb = *(const float4*)(rrow + q * 8 + 4);
                float a[8];
                a[0] = __expf(v0.x - ma.x) * ra.x;  a[1] = __expf(v0.y - ma.y) * ra.y;
                a[2] = __expf(v0.z - ma.z) * ra.z;  a[3] = __expf(v0.w - ma.w) * ra.w;
                a[4] = __expf(v1.x - mb.x) * rb.x;  a[5] = __expf(v1.y - mb.y) * rb.y;
                a[6] = __expf(v1.z - mb.z) * rb.z;  a[7] = __expf(v1.w - mb.w) * rb.w;
                __nv_bfloat16 hv[8], lv[8];
                #pragma unroll
                for (int e = 0; e < 8; e++) {
                    hv[e] = __float2bfloat16(a[e]);
                    lv[e] = __float2bfloat16(a[e] - __bfloat162float(hv[e]));
                }
                uint32_t off = (uint32_t)er * 128 + eh * 64 + q * 16;
                uint32_t sw = off ^ ((off >> 3) & 0x70);
                *(uint4*)(smem + AHI_OFF + sw) = *(uint4*)hv;
                *(uint4*)(smem + ALO_OFF + sw) = *(uint4*)lv;
            }
        }
        __syncthreads();
        // prefetch next iteration (single group: EST -> stg, VT -> other V buffer)
        if (jb + 1 < 32) {
            LOAD_EST(jb + 1);
            LOAD_VT(jb + 1, (jb + 1) & 1);
            cp_commit();
        }
        // --- MMA phase: 3 compensation terms on current V buffer
        uint32_t vcur = sb + VBASE + (jb & 1) * 32768;
        const uint32_t aT[3] = {sb + AHI_OFF, sb + ALO_OFF, sb + AHI_OFF};
        const uint32_t bT[3] = {vcur, vcur, vcur + 16384};
        #pragma unroll
        for (int t = 0; t < 3; t++) {
            uint32_t aB = aT[t], bB = bT[t];
            #pragma unroll
            for (int ks = 0; ks < 4; ks++) {
                uint32_t kcol = (uint32_t)ks * 32;
                uint32_t afr[2][4], bfr[4][4];
                #pragma unroll
                for (int mi = 0; mi < 2; mi++) {
                    uint32_t off = aoff[mi] + kcol + ake;
                    ldsm4(afr[mi], aB + (off ^ ((off >> 3) & 0x70)));
                }
                #pragma unroll
                for (int bi = 0; bi < 4; bi++) {
                    uint32_t off = boff[bi] + kcol + bke;
                    ldsm4(bfr[bi], bB + (off ^ ((off >> 3) & 0x70)));
                }
                #pragma unroll
                for (int mi = 0; mi < 2; mi++)
                    #pragma unroll
                    for (int ni = 0; ni < 8; ni++)
                        mma16816(acc[mi][ni], afr[mi], &bfr[ni >> 1][(ni & 1) * 2]);
            }
        }
    }

    // --- epilogue: write Yaug (hi, lo, hi) directly
    #pragma unroll
    for (int mi = 0; mi < 2; mi++) {
        #pragma unroll
        for (int half = 0; half < 2; half++) {
            int rr = warp_m + mi * 16 + (lane >> 2) + half * 8;
            __nv_bfloat16* Yr = g_Yaug + ((long)(b * NSEQ + m0 + rr)) * 3072 + h * DH;
            #pragma unroll
            for (int ni = 0; ni < 8; ni++) {
                int col = warp_n + ni * 8 + (lane & 3) * 2;
                float y0 = acc[mi][ni][half * 2 + 0];
                float y1 = acc[mi][ni][half * 2 + 1];
                __nv_bfloat16 h0 = __float2bfloat16(y0);
                __nv_bfloat16 h1 = __float2bfloat16(y1);
                __nv_bfloat16 l0 = __float2bfloat16(y0 - __bfloat162float(h0));
                __nv_bfloat16 l1 = __float2bfloat16(y1 - __bfloat162float(h1));
                __nv_bfloat162 hi2; hi2.x = h0; hi2.y = h1;
                __nv_bfloat162 lo2; lo2.x = l0; lo2.y = l1;
                *(__nv_bfloat162*)&Yr[col] = hi2;
                *(__nv_bfloat162*)&Yr[1024 + col] = lo2;
                *(__nv_bfloat162*)&Yr[2048 + col] = hi2;
            }
        }
    }
}

// ----------------------------- launch ---------------------------------------
extern "C" void kernel_launch(void* const* d_in, const int* in_sizes, int n_in,
                              void* d_out, int out_size) {
    const float* x    = (const float*)d_in[0];
    const int*   mask = (const int*)d_in[1];
    const float* Wq   = (const float*)d_in[2];
    const float* Wk   = (const float*)d_in[3];
    const float* Wv   = (const float*)d_in[4];
    const float* Wout = (const float*)d_in[5];
    float* out = (float*)d_out;

    const long long out_elems = (long long)BB * NSEQ * DMODEL;
    const long long att_elems = (long long)BB * NSEQ * NSEQ;
    float* outA = ((long long)out_size >= out_elems + att_elems) ? out + out_elems : nullptr;

    cudaFuncSetAttribute(gemm_kernel, cudaFuncAttributeMaxDynamicSharedMemorySize, GSMEM);
    cudaFuncSetAttribute(atv_kernel, cudaFuncAttributeMaxDynamicSharedMemorySize, ATV_SMEM);

    __nv_bfloat16 *p_xaug, *p_Waug, *p_Woutaug, *p_Qaug, *p_Kaug, *p_Yaug;
    float *p_P, *p_E;
    cudaGetSymbolAddress((void**)&p_xaug, g_xaug);
    cudaGetSymbolAddress((void**)&p_Waug, g_Waug);
    cudaGetSymbolAddress((void**)&p_Woutaug, g_Woutaug);
    cudaGetSymbolAddress((void**)&p_Qaug, g_Qaug);
    cudaGetSymbolAddress((void**)&p_Kaug, g_Kaug);
    cudaGetSymbolAddress((void**)&p_Yaug, g_Yaug);
    cudaGetSymbolAddress((void**)&p_P, g_P);
    cudaGetSymbolAddress((void**)&p_E, g_E);

    // launches 1-5: splits (so launch #6 = QKV GEMM is what ncu -s 5 -c 1 profiles)
    split_kernel<<<(8192 * 1024) / 256, 256>>>(x, p_xaug, 1024, 1, 8192 * 1024);
    split_kernel<<<(1024 * 1024) / 256, 256>>>(Wq,   p_Waug,               1024, 0, 1024 * 1024);
    split_kernel<<<(1024 * 1024) / 256, 256>>>(Wk,   p_Waug + 1024 * 3072, 1024, 0, 1024 * 1024);
    split_kernel<<<(1024 * 1024) / 256, 256>>>(Wv,   p_Waug + 2048 * 3072, 1024, 0, 1024 * 1024);
    split_kernel<<<(1024 * 1024) / 256, 256>>>(Wout, p_Woutaug,            1024, 0, 1024 * 1024);

    // QKV projection  (launch #6 — profiled)
    gemm_kernel<<<dim3(3072 / 128, 8192 / 128, 1), 256, GSMEM>>>(
        p_xaug, 0, 3072, p_Waug, 0, 3072, 3072, 0, p_P, 0, 3072, mask);

    apt_kernel<<<(NSEQ * NSEQ) / 256, 256>>>();
    qksplit_kernel<<<(1 << 23) / 256, 256>>>();
    vtrans_kernel<<<dim3(NSEQ / 32, DH / 32, 32), 256>>>();

    // E^T = (K Q^T) + AP^T, masked; fused per-column stats partials
    gemm_kernel<<<dim3(NSEQ / 128, NSEQ / 128, 32), 256, GSMEM>>>(
        p_Kaug, (long)NSEQ * 384, 384, p_Qaug, (long)NSEQ * 384, 384,
        384, 1, p_E, (long)NSEQ * NSEQ, NSEQ, mask);

    stats_reduce_kernel<<<(32 * NSEQ) / 256, 256>>>();
    if (outA) outa_kernel<<<dim3(NSEQ / 32, NSEQ / 32, BB), 256>>>(outA);

    // fused Y = A^T V  -> writes Yaug directly
    atv_kernel<<<dim3(16, 32), 256, ATV_SMEM>>>();

    // out = Y Wout^T
    gemm_kernel<<<dim3(1024 / 128, 8192 / 128, 1), 256, GSMEM>>>(
        p_Yaug, 0, 3072, p_Woutaug, 0, 3072, 3072, 0, out, 0, 1024, mask);
}